// round 17
// baseline (speedup 1.0000x reference)
#include <cuda_runtime.h>
#include <cuda_fp16.h>
#include <cstdint>

// Problem constants
#define BATCH 64
#define DDIM  4096
#define SDIM  128
#define NTOK  256
#define NCHUNK 128             // D/32 k-chunks
#define NN_MINUS_N 65280.0f    // n^2-n, n=256

// X-chunk smem: 32 k-rows x 256 tokens fp16, rows padded 512->528 B
#define XROWB 528
#define XTILE (32 * XROWB)     // 16896 B per part (hi or lo)
#define XSTG  (2 * XTILE)      // 33792 B per stage
#define NSTAGE 3

// Pre-split fp16 hi/lo, fused token layout: [b][d][tok 0..255], 512 B rows
__device__ uint2 g_hi[(size_t)BATCH * DDIM * 64];
__device__ uint2 g_lo[(size_t)BATCH * DDIM * 64];

__device__ float g_sq[BATCH * NTOK];
__device__ float g_bwA[BATCH];
__device__ float g_sq_part[BATCH * 8 * NTOK];
__device__ float g_bwA_part[BATCH * 8];
__device__ float g_part[BATCH * 4];

// 36 unique 32x32 blocks of the symmetric 256x256 Gram (bi<=bj), 4 CTAs x 9 warps
__constant__ unsigned char c_BI[36] = {0,0,0,0,0,0,0,0, 1,1,1,1,1,1,1, 2,2,2,2,2,2,
                                       3,3,3,3,3, 4,4,4,4, 5,5,5, 6,6, 7};
__constant__ unsigned char c_BJ[36] = {0,1,2,3,4,5,6,7, 1,2,3,4,5,6,7, 2,3,4,5,6,7,
                                       3,4,5,6,7, 4,5,6,7, 5,6,7, 6,7, 7};

static __device__ __forceinline__ uint32_t smem_u32(const void* p) {
    uint32_t a;
    asm("{ .reg .u64 t; cvta.to.shared.u64 t, %1; cvt.u32.u64 %0, t; }" : "=r"(a) : "l"(p));
    return a;
}
static __device__ __forceinline__ void cp16(uint32_t dst, const void* src) {
    asm volatile("cp.async.ca.shared.global [%0], [%1], 16;" :: "r"(dst), "l"(src) : "memory");
}
static __device__ __forceinline__ void mma_f16(float* c, const uint32_t* a, const uint32_t* b) {
    asm volatile(
        "mma.sync.aligned.m16n8k16.row.col.f32.f16.f16.f32 "
        "{%0,%1,%2,%3}, {%4,%5,%6,%7}, {%8,%9}, {%0,%1,%2,%3};"
        : "+f"(c[0]), "+f"(c[1]), "+f"(c[2]), "+f"(c[3])
        : "r"(a[0]), "r"(a[1]), "r"(a[2]), "r"(a[3]), "r"(b[0]), "r"(b[1]));
}
static __device__ __forceinline__ void ldsm4t(uint32_t* r, uint32_t addr) {
    asm volatile("ldmatrix.sync.aligned.m8n8.x4.trans.shared.b16 {%0,%1,%2,%3}, [%4];"
                 : "=r"(r[0]), "=r"(r[1]), "=r"(r[2]), "=r"(r[3]) : "r"(addr));
}

// ---------------------------------------------------------------------------
// K0: no-op (keeps ncu's captured launch on the gram kernel)
// ---------------------------------------------------------------------------
__global__ void noop_kernel() {}

// ---------------------------------------------------------------------------
// K1: fused prep (fp32 -> fp16 hi/lo, fused token rows) + stats partials.
// grid (8 segs, 64 batches), 512 d-rows per CTA, 256 threads.
// ---------------------------------------------------------------------------
__global__ __launch_bounds__(256) void prep_stats(const float* __restrict__ src,
                                                  const float* __restrict__ tgt)
{
    int seg = blockIdx.x, b = blockIdx.y;
    int warp = threadIdx.x >> 5, lane = threadIdx.x & 31;

    const float4* sb = (const float4*)(src + (size_t)b * DDIM * SDIM);
    const float4* tb = (const float4*)(tgt + (size_t)b * DDIM * SDIM);

    float sqloc[8];
#pragma unroll
    for (int q = 0; q < 8; q++) sqloc[q] = 0.0f;
    float accA = 0.0f;

#pragma unroll 2
    for (int it = 0; it < 64; it++) {
        int d = seg * 512 + it * 8 + warp;
        size_t gi = (size_t)(b * DDIM + d) * 64 + lane;
        float4 vs = sb[d * 32 + lane];
        float4 vt = tb[d * 32 + lane];

        {
            __half2 h0 = __floats2half2_rn(vs.x, vs.y);
            __half2 h1 = __floats2half2_rn(vs.z, vs.w);
            __half2 l0 = __floats2half2_rn(vs.x - __low2float(h0), vs.y - __high2float(h0));
            __half2 l1 = __floats2half2_rn(vs.z - __low2float(h1), vs.w - __high2float(h1));
            uint2 hv, lv;
            hv.x = *(uint32_t*)&h0; hv.y = *(uint32_t*)&h1;
            lv.x = *(uint32_t*)&l0; lv.y = *(uint32_t*)&l1;
            g_hi[gi] = hv; g_lo[gi] = lv;
        }
        {
            __half2 h0 = __floats2half2_rn(vt.x, vt.y);
            __half2 h1 = __floats2half2_rn(vt.z, vt.w);
            __half2 l0 = __floats2half2_rn(vt.x - __low2float(h0), vt.y - __high2float(h0));
            __half2 l1 = __floats2half2_rn(vt.z - __low2float(h1), vt.w - __high2float(h1));
            uint2 hv, lv;
            hv.x = *(uint32_t*)&h0; hv.y = *(uint32_t*)&h1;
            lv.x = *(uint32_t*)&l0; lv.y = *(uint32_t*)&l1;
            g_hi[gi + 32] = hv; g_lo[gi + 32] = lv;
        }

        float v[8] = {vs.x, vs.y, vs.z, vs.w, vt.x, vt.y, vt.z, vt.w};
        float s1 = 0.0f, s2 = 0.0f;
#pragma unroll
        for (int q = 0; q < 8; q++) {
            s1 += v[q];
            float p = v[q] * v[q];
            s2 += p;
            sqloc[q] += p;
        }
#pragma unroll
        for (int o = 16; o; o >>= 1) {
            s1 += __shfl_xor_sync(0xffffffffu, s1, o);
            s2 += __shfl_xor_sync(0xffffffffu, s2, o);
        }
        if (lane == 0) accA += 2.0f * (float)NTOK * s2 - 2.0f * s1 * s1;
    }

    __shared__ float ssq[8][NTOK];
    __shared__ float sA[8];
#pragma unroll
    for (int q = 0; q < 8; q++) {
        int i = (q < 4) ? (4 * lane + q) : (SDIM + 4 * lane + (q - 4));
        ssq[warp][i] = sqloc[q];
    }
    if (lane == 0) sA[warp] = accA;
    __syncthreads();

    {
        int i = threadIdx.x;
        float s = 0.0f;
#pragma unroll
        for (int wq = 0; wq < 8; wq++) s += ssq[wq][i];
        g_sq_part[(size_t)(b * 8 + seg) * NTOK + i] = s;
    }
    if (threadIdx.x == 0) {
        float A = 0.0f;
#pragma unroll
        for (int wq = 0; wq < 8; wq++) A += sA[wq];
        g_bwA_part[b * 8 + seg] = A;
    }
}

__global__ void stats_combine()
{
    int b = blockIdx.x, t = threadIdx.x;
    float s = 0.0f;
#pragma unroll
    for (int seg = 0; seg < 8; seg++) s += g_sq_part[(size_t)(b * 8 + seg) * NTOK + t];
    g_sq[b * NTOK + t] = s;
    if (t == 0) {
        float A = 0.0f;
#pragma unroll
        for (int seg = 0; seg < 8; seg++) A += g_bwA_part[b * 8 + seg];
        g_bwA[b] = A;
    }
}

// ---------------------------------------------------------------------------
// K2: symmetric-block Gram. grid (4 CTAs, 64 batches), 288 threads (9 warps).
// 3-stage cp.async ring, 1 sync/chunk; all 16 ldsm front-loaded per chunk.
// ---------------------------------------------------------------------------
extern __shared__ char dynsmem[];

static __device__ __forceinline__ void load_sym(uint32_t stg, const char* hb,
                                                const char* lb, int d0, int t)
{
#pragma unroll
    for (int i = 0; i < 8; i++) {
        int s = t + i * 288;
        if (s < 2048) {
            int part = s >> 10;           // 0 hi, 1 lo
            int r    = s & 1023;
            int row  = r >> 5;            // 0..31
            int ck   = (r & 31) << 4;     // 0..496
            const char* src = (part ? lb : hb) + (size_t)(d0 + row) * 512 + ck;
            cp16(stg + part * XTILE + row * XROWB + ck, src);
        }
    }
}

__global__ __launch_bounds__(288, 2) void gram_sym(int dummy)
{
    const int q   = blockIdx.x;
    const int b   = blockIdx.y;
    const int t   = threadIdx.x;
    const int wid = t >> 5;        // 0..8
    const int lid = t & 31;
    const int gid = lid >> 2;
    const int kq  = lid & 3;

    const int blk = q * 9 + wid;
    const int bi  = c_BI[blk];
    const int bj  = c_BJ[blk];
    const float wsign = ((bi < 4) == (bj < 4)) ? 2.0f : -2.0f;
    const bool isdiag = (bi == bj);

    const char* hb = (const char*)g_hi + (size_t)b * DDIM * 512;
    const char* lb = (const char*)g_lo + (size_t)b * DDIM * 512;

    __shared__ float sq_sh[NTOK];
    __shared__ float wsum[9];
    if (t < NTOK) sq_sh[t] = g_sq[b * NTOK + t];

    const uint32_t sb = smem_u32(dynsmem);

    // ldmatrix lane-offsets (proven R11/R14 mapping)
    const int krA = (lid & 7) + ((lid >> 4) & 1) * 8;
    const int tkA = ((lid >> 3) & 1) * 8;
    const int krB = (lid & 7) + ((lid >> 3) & 1) * 8;
    const int tkB = ((lid >> 4) & 1) * 8;

    float acc[2][4][4];
#pragma unroll
    for (int mt = 0; mt < 2; mt++)
#pragma unroll
        for (int nt = 0; nt < 4; nt++)
#pragma unroll
            for (int r = 0; r < 4; r++) acc[mt][nt][r] = 0.0f;

    // prologue: stages 0 and 1
    load_sym(sb, hb, lb, 0, t);
    asm volatile("cp.async.commit_group;" ::: "memory");
    load_sym(sb + XSTG, hb, lb, 32, t);
    asm volatile("cp.async.commit_group;" ::: "memory");

    uint32_t stg = sb;                    // stage of chunk c
    uint32_t stg_next2 = sb + 2 * XSTG;   // stage (c+2)%3

    for (int c = 0; c < NCHUNK; c++) {
        if (c < NCHUNK - 1) {
            asm volatile("cp.async.wait_group 1;" ::: "memory");
        } else {
            asm volatile("cp.async.wait_group 0;" ::: "memory");
        }
        __syncthreads();   // chunk c data visible to all; stage (c+2)%3 free

        if (c + 2 < NCHUNK) {
            load_sym(stg_next2, hb, lb, (c + 2) * 32, t);
            asm volatile("cp.async.commit_group;" ::: "memory");
        }

        // ---- front-load ALL fragments for this chunk (16 ldsm) ----
        uint32_t aH[2][2][4], aL[2][2][4];   // [ks][mt]
        uint32_t bH[2][2][4], bL[2][2][4];   // [ks][np]
#pragma unroll
        for (int ks = 0; ks < 2; ks++) {
#pragma unroll
            for (int mt = 0; mt < 2; mt++) {
                uint32_t ar = stg + (ks * 16 + krA) * XROWB +
                              (bi * 32 + mt * 16 + tkA) * 2;
                ldsm4t(aH[ks][mt], ar);
                ldsm4t(aL[ks][mt], ar + XTILE);
            }
#pragma unroll
            for (int np = 0; np < 2; np++) {
                uint32_t br = stg + (ks * 16 + krB) * XROWB +
                              (bj * 32 + np * 16 + tkB) * 2;
                ldsm4t(bH[ks][np], br);
                ldsm4t(bL[ks][np], br + XTILE);
            }
        }

        // ---- MMA burst (48) ----
#pragma unroll
        for (int ks = 0; ks < 2; ks++)
#pragma unroll
            for (int np = 0; np < 2; np++)
#pragma unroll
                for (int mt = 0; mt < 2; mt++)
#pragma unroll
                    for (int nl = 0; nl < 2; nl++) {
                        float* a = acc[mt][np * 2 + nl];
                        mma_f16(a, aH[ks][mt], bH[ks][np] + 2 * nl);
                        mma_f16(a, aH[ks][mt], bL[ks][np] + 2 * nl);
                        mma_f16(a, aL[ks][mt], bH[ks][np] + 2 * nl);
                    }

        // rotate stages
        uint32_t s0 = stg;
        stg = (stg == sb + 2 * XSTG) ? sb : stg + XSTG;
        stg_next2 = s0;
    }

    // ---- fused symmetric MMD epilogue ----
    float bw = g_bwA[b] * (1.0f / NN_MINUS_N) * 0.25f;
    float c4 = -1.0f / (16.0f * bw);

    float psum = 0.0f;
#pragma unroll
    for (int mt = 0; mt < 2; mt++) {
#pragma unroll
        for (int nt = 0; nt < 4; nt++) {
#pragma unroll
            for (int r = 0; r < 4; r++) {
                int il = mt * 16 + gid + ((r >> 1) & 1) * 8;
                int jl = (nt >> 1) * 16 + (nt & 1) * 8 + 2 * kq + (r & 1);
                if (!isdiag || jl > il) {
                    float L2 = sq_sh[bi * 32 + il] + sq_sh[bj * 32 + jl]
                               - 2.0f * acc[mt][nt][r];
                    float e1 = __expf(L2 * c4);
                    float e2 = e1 * e1, e4 = e2 * e2, e8 = e4 * e4, e16 = e8 * e8;
                    psum += e1 + e2 + e4 + e8 + e16;
                }
            }
        }
    }
    psum *= wsign;

#pragma unroll
    for (int o = 16; o; o >>= 1) psum += __shfl_xor_sync(0xffffffffu, psum, o);
    if (lid == 0) wsum[wid] = psum;
    __syncthreads();
    if (t == 0) {
        float s = 0.0f;
#pragma unroll
        for (int i = 0; i < 9; i++) s += wsum[i];
        g_part[b * 4 + q] = s;
    }
}

// ---------------------------------------------------------------------------
// K3: finalize (+ analytic diagonal 256*5*64 = 81920; normalize /B/128/128)
// ---------------------------------------------------------------------------
__global__ void finalize_kernel(float* __restrict__ out)
{
    __shared__ float red[256];
    int t = threadIdx.x;
    red[t] = g_part[t];
    __syncthreads();
#pragma unroll
    for (int s = 128; s > 0; s >>= 1) {
        if (t < s) red[t] += red[t + s];
        __syncthreads();
    }
    if (t == 0) out[0] = (red[0] + 81920.0f) * (1.0f / 1048576.0f);
}

extern "C" void kernel_launch(void* const* d_in, const int* in_sizes, int n_in,
                              void* d_out, int out_size)
{
    const float* src = (const float*)d_in[0];
    const float* tgt = (const float*)d_in[1];
    float* out = (float*)d_out;

    static bool configured = false;
    if (!configured) {
        cudaFuncSetAttribute(gram_sym, cudaFuncAttributeMaxDynamicSharedMemorySize,
                             NSTAGE * XSTG);
        configured = true;
    }

    noop_kernel<<<1, 32>>>();
    prep_stats<<<dim3(8, BATCH), 256>>>(src, tgt);
    stats_combine<<<BATCH, 256>>>();
    gram_sym<<<dim3(4, BATCH), 288, NSTAGE * XSTG>>>(0);
    finalize_kernel<<<1, 256>>>(out);
}